// round 10
// baseline (speedup 1.0000x reference)
#include <cuda_runtime.h>
#include <math.h>
#include <stdint.h>

#define B_ 8
#define C_ 16
#define S_ 512
#define E_ 256
#define BC_ 128
#define EW  128   // bf16x2 words per row (E/2)
#define SP_ 256   // s-pairs (S/2)

// bf16 scratch: q/k as [s][e-pair]; v TRANSPOSED: [f][s-pair]
__device__ uint32_t g_q[(size_t)BC_ * S_ * EW];
__device__ uint32_t g_k[(size_t)BC_ * S_ * EW];
__device__ uint32_t g_v[(size_t)BC_ * E_ * SP_];

// ---------------------------------------------------------------------------
// helpers
// ---------------------------------------------------------------------------
__device__ __forceinline__ uint32_t pk2(float lo, float hi) {
    uint32_t r;
    asm("cvt.rn.bf16x2.f32 %0, %1, %2;" : "=r"(r) : "f"(hi), "f"(lo));
    return r;
}
__device__ __forceinline__ uint2 pk4(float4 v) {
    uint2 u; u.x = pk2(v.x, v.y); u.y = pk2(v.z, v.w); return u;
}
__device__ __forceinline__ void mma16(float* c, const uint32_t* a, const uint32_t* b) {
    asm volatile(
        "mma.sync.aligned.m16n8k16.row.col.f32.bf16.bf16.f32 "
        "{%0,%1,%2,%3}, {%4,%5,%6,%7}, {%8,%9}, {%0,%1,%2,%3};"
        : "+f"(c[0]), "+f"(c[1]), "+f"(c[2]), "+f"(c[3])
        : "r"(a[0]), "r"(a[1]), "r"(a[2]), "r"(a[3]), "r"(b[0]), "r"(b[1]));
}
__device__ __forceinline__ void ldsm4(uint32_t* r, uint32_t addr) {
    asm volatile("ldmatrix.sync.aligned.m8n8.x4.shared.b16 {%0,%1,%2,%3}, [%4];"
                 : "=r"(r[0]), "=r"(r[1]), "=r"(r[2]), "=r"(r[3]) : "r"(addr));
}
__device__ __forceinline__ void cpa16(uint32_t smem_addr, const void* gptr) {
    asm volatile("cp.async.cg.shared.global [%0], [%1], 16;"
                 :: "r"(smem_addr), "l"(gptr));
}
#define CP_COMMIT() asm volatile("cp.async.commit_group;")
#define CP_WAIT0()  asm volatile("cp.async.wait_group 0;")
#define CP_WAIT1()  asm volatile("cp.async.wait_group 1;")
#define CP_WAIT2()  asm volatile("cp.async.wait_group 2;")

// ---------------------------------------------------------------------------
// Projection v3 (merged q/k/v): 512 threads, 16 warps (4m x 4n), warp tile
// 32x32, k-chunk 64. Register-prefetch software pipeline hides LDG latency.
// ---------------------------------------------------------------------------
#define PA  36
#define PBP 136
#define PT  68

__global__ __launch_bounds__(512) void proj_kernel(
    const float* __restrict__ query, const float* __restrict__ key,
    const float* __restrict__ value,
    const float* __restrict__ wq, const float* __restrict__ wk,
    const float* __restrict__ wv,
    const float* __restrict__ bq, const float* __restrict__ bk,
    const float* __restrict__ bv, float qscale)
{
    __shared__ uint32_t pool[8960];      // sA(4608)+sB(4352); sT(8704) overlay
    uint32_t* sA = pool;
    uint32_t* sB = pool + 4608;
    uint32_t* sT = pool;

    const int zi    = blockIdx.z;
    const int which = zi >> 7;
    const int bc    = zi & (BC_ - 1);
    const int c     = bc % C_;

    const float *X, *W, *bp;
    uint32_t* Yw;
    float scale;
    if (which == 0)      { X = query; W = wq; bp = bq; Yw = g_q + (size_t)bc * S_ * EW; scale = qscale; }
    else if (which == 1) { X = key;   W = wk; bp = bk; Yw = g_k + (size_t)bc * S_ * EW; scale = 1.0f; }
    else                 { X = value; W = wv; bp = bv; Yw = g_v + (size_t)bc * E_ * SP_; scale = 1.0f; }
    X  += (size_t)bc * S_ * E_;
    W  += (size_t)c  * E_ * E_;
    bp += (size_t)c  * E_;

    const int m0 = blockIdx.x * 128;
    const int n0 = blockIdx.y * 128;
    const int t  = threadIdx.x;
    const int warp = t >> 5;
    const int wm   = warp >> 2;    // 0..3
    const int wn   = warp & 3;     // 0..3
    const int lane = t & 31;
    const int g = lane >> 2;
    const int q = lane & 3;

    const int arow  = (lane & 7) + (((lane >> 3) & 1) << 3);
    const int akadd = (lane >> 4) << 2;
    const uint32_t smbA = (uint32_t)__cvta_generic_to_shared(sA);
    const uint32_t aBase = smbA + (uint32_t)((wm * 32 + arow) * PA + akadd) * 4u;

    // load indices (fixed per thread)
    const int xrow = t >> 4,  xc4 = (t & 15) << 2;           // +32 rows per iter
    const int wkp  = t >> 5,  wn4 = (t & 31) << 2;           // +16 kp per iter

    float acc[2][4][4];
    #pragma unroll
    for (int i = 0; i < 2; i++)
        #pragma unroll
        for (int j = 0; j < 4; j++)
            #pragma unroll
            for (int r = 0; r < 4; r++) acc[i][j][r] = 0.0f;

    float4 xr[4];          // X prefetch: 4 rows-groups
    float4 wr0[2], wr1[2]; // W prefetch: 2 kp-groups x 2 rows

    // prologue: prefetch chunk 0
    #pragma unroll
    for (int i = 0; i < 4; i++)
        xr[i] = *(const float4*)&X[(size_t)(m0 + xrow + 32 * i) * E_ + xc4];
    #pragma unroll
    for (int i = 0; i < 2; i++) {
        wr0[i] = *(const float4*)&W[(size_t)(2 * (wkp + 16 * i))     * E_ + n0 + wn4];
        wr1[i] = *(const float4*)&W[(size_t)(2 * (wkp + 16 * i) + 1) * E_ + n0 + wn4];
    }

    #pragma unroll 1
    for (int ck = 0; ck < 4; ck++) {
        // store prefetched chunk to smem (cvt to bf16)
        #pragma unroll
        for (int i = 0; i < 4; i++)
            *(uint2*)&sA[(xrow + 32 * i) * PA + (xc4 >> 1)] = pk4(xr[i]);
        #pragma unroll
        for (int i = 0; i < 2; i++) {
            uint4 u;
            u.x = pk2(wr0[i].x, wr1[i].x); u.y = pk2(wr0[i].y, wr1[i].y);
            u.z = pk2(wr0[i].z, wr1[i].z); u.w = pk2(wr0[i].w, wr1[i].w);
            *(uint4*)&sB[(wkp + 16 * i) * PBP + wn4] = u;
        }
        __syncthreads();

        // prefetch next chunk (overlaps mma below)
        if (ck < 3) {
            const int k0 = 64 * (ck + 1);
            #pragma unroll
            for (int i = 0; i < 4; i++)
                xr[i] = *(const float4*)&X[(size_t)(m0 + xrow + 32 * i) * E_ + k0 + xc4];
            #pragma unroll
            for (int i = 0; i < 2; i++) {
                wr0[i] = *(const float4*)&W[(size_t)(k0 + 2 * (wkp + 16 * i))     * E_ + n0 + wn4];
                wr1[i] = *(const float4*)&W[(size_t)(k0 + 2 * (wkp + 16 * i) + 1) * E_ + n0 + wn4];
            }
        }

        #pragma unroll
        for (int kkp = 0; kkp < 32; kkp += 8) {
            uint32_t a[2][4], b[4][2];
            #pragma unroll
            for (int mt = 0; mt < 2; mt++)
                ldsm4(a[mt], aBase + (uint32_t)(mt * 16 * PA + kkp) * 4u);
            #pragma unroll
            for (int nt = 0; nt < 4; nt++) {
                const int n = wn * 32 + nt * 8 + g;
                b[nt][0] = sB[(kkp + q) * PBP + n];
                b[nt][1] = sB[(kkp + q + 4) * PBP + n];
            }
            #pragma unroll
            for (int mt = 0; mt < 2; mt++)
                #pragma unroll
                for (int nt = 0; nt < 4; nt++)
                    mma16(acc[mt][nt], a[mt], b[nt]);
        }
        __syncthreads();
    }

    // Epilogue
    if (which != 2) {
        #pragma unroll
        for (int nt = 0; nt < 4; nt++) {
            const int col = n0 + wn * 32 + nt * 8 + 2 * q;
            const float b0v = bp[col], b1v = bp[col + 1];
            #pragma unroll
            for (int mt = 0; mt < 2; mt++) {
                const int row = m0 + wm * 32 + mt * 16 + g;
                const float v00 = fmaxf(acc[mt][nt][0] + b0v, 0.0f) * scale;
                const float v01 = fmaxf(acc[mt][nt][1] + b1v, 0.0f) * scale;
                const float v10 = fmaxf(acc[mt][nt][2] + b0v, 0.0f) * scale;
                const float v11 = fmaxf(acc[mt][nt][3] + b1v, 0.0f) * scale;
                const int cw = (n0 >> 1) + wn * 16 + nt * 4 + q;
                Yw[(size_t)row * EW + cw]       = pk2(v00, v01);
                Yw[(size_t)(row + 8) * EW + cw] = pk2(v10, v11);
            }
        }
    } else {
        #pragma unroll
        for (int nt = 0; nt < 4; nt++) {
            const int col = n0 + wn * 32 + nt * 8 + 2 * q;
            const float b0v = bp[col], b1v = bp[col + 1];
            #pragma unroll
            for (int mt = 0; mt < 2; mt++) {
                const float v00 = fmaxf(acc[mt][nt][0] + b0v, 0.0f);
                const float v01 = fmaxf(acc[mt][nt][1] + b1v, 0.0f);
                const float v10 = fmaxf(acc[mt][nt][2] + b0v, 0.0f);
                const float v11 = fmaxf(acc[mt][nt][3] + b1v, 0.0f);
                const float p00 = __shfl_xor_sync(0xFFFFFFFFu, v00, 4);
                const float p01 = __shfl_xor_sync(0xFFFFFFFFu, v01, 4);
                const float p10 = __shfl_xor_sync(0xFFFFFFFFu, v10, 4);
                const float p11 = __shfl_xor_sync(0xFFFFFFFFu, v11, 4);
                if ((g & 1) == 0) {
                    const int lcol = wn * 32 + nt * 8 + 2 * q;
                    const int lsp  = (wm * 32 + mt * 16 + g) >> 1;
                    sT[lcol * PT + lsp]           = pk2(v00, p00);
                    sT[(lcol + 1) * PT + lsp]     = pk2(v01, p01);
                    sT[lcol * PT + lsp + 4]       = pk2(v10, p10);
                    sT[(lcol + 1) * PT + lsp + 4] = pk2(v11, p11);
                }
            }
        }
        __syncthreads();
        const int spb = m0 >> 1;
        #pragma unroll
        for (int i = 0; i < 4; i++) {
            const int o = t + 512 * i;
            const int col = o >> 4, j = o & 15;
            *(uint4*)&Yw[(size_t)(n0 + col) * SP_ + spb + j * 4] =
                *(uint4*)&sT[col * PT + j * 4];
        }
    }
}

// ---------------------------------------------------------------------------
// Attention v5: 64 q-rows/CTA, 512 threads (2m x 8n), scores in registers,
// 4-stage cp.async pipelines for K and V, ldmatrix operands.
// ---------------------------------------------------------------------------
#define PQF 132
#define PKC 20
#define SPP 260
#define PVT 36

#define OFF_SQ 0             // 64*132 = 8448
#define OFF_K  8448          // 4 x 10240 -> ends 49408
#define KSTR   10240
#define OFF_SS 0             // 64*260 = 16640 (overlay)
#define OFF_V  16640         // 4 x 9216 -> ends 53504
#define VSTR   9216
#define OFF_RD 53504         // 1024 floats
#define ATT_WORDS 54528      // 218112 B

__global__ __launch_bounds__(512, 1) void attn_kernel(float* __restrict__ out)
{
    extern __shared__ uint32_t smu[];
    uint32_t* sQ = smu + OFF_SQ;
    uint32_t* sS = smu + OFF_SS;
    float* sRedM = (float*)(smu + OFF_RD);         // [64 rows][8 wn]
    float* sRedS = (float*)(smu + OFF_RD + 512);

    const uint32_t smb = (uint32_t)__cvta_generic_to_shared(smu);

    const int bc = blockIdx.y;
    const int q0 = blockIdx.x * 64;
    const uint32_t* Qw = g_q + (size_t)bc * S_ * EW;
    const uint32_t* Kw = g_k + (size_t)bc * S_ * EW;
    const uint32_t* Vw = g_v + (size_t)bc * E_ * SP_;
    float*          O  = out + (size_t)bc * S_ * E_;

    const int t    = threadIdx.x;
    const int warp = t >> 5;
    const int wm   = warp >> 3;
    const int wn   = warp & 7;
    const int lane = t & 31;
    const int g = lane >> 2;
    const int q = lane & 3;

    const int arow  = (lane & 7) + (((lane >> 3) & 1) << 3);
    const int akadd = (lane >> 4) << 2;
    const int brow  = (lane & 7) + ((lane >> 4) << 3);
    const int bkadd = ((lane >> 3) & 1) << 2;

    const uint32_t aQbase = smb + (uint32_t)(OFF_SQ + (wm * 32 + arow) * PQF + akadd) * 4u;
    const uint32_t aSbase = smb + (uint32_t)(OFF_SS + (wm * 32 + arow) * SPP + akadd) * 4u;
    const uint32_t bKoff  = (uint32_t)(brow * PKC + bkadd) * 4u;
    const uint32_t bVoff  = (uint32_t)(brow * PVT + bkadd) * 4u;

    // ---- issue K chunks 0,1,2 (4-stage prologue) -------------------------
    #pragma unroll
    for (int pc = 0; pc < 3; pc++) {
        const uint32_t dst = smb + (uint32_t)(OFF_K + pc * KSTR) * 4u;
        const int ecp = pc * 16;
        #pragma unroll
        for (int i = 0; i < 4; i++) {
            const int o = t + 512 * i;
            const int s = o >> 2, jj = o & 3;
            cpa16(dst + (uint32_t)(s * PKC + jj * 4) * 4u,
                  Kw + (size_t)s * EW + ecp + jj * 4);
        }
        CP_COMMIT();
    }

    // ---- stage whole Q tile (64 x 128 words) -----------------------------
    #pragma unroll
    for (int i = 0; i < 4; i++) {
        const int o = t + 512 * i;
        const int row = o >> 5, j = o & 31;
        *(uint4*)&sQ[row * PQF + j * 4] =
            *(const uint4*)&Qw[(size_t)(q0 + row) * EW + j * 4];
    }

    // ---------------- Phase 1: scores = Q K^T ------------------------------
    float acc[2][8][4];
    #pragma unroll
    for (int mt = 0; mt < 2; mt++)
        #pragma unroll
        for (int nt = 0; nt < 8; nt++)
            #pragma unroll
            for (int r = 0; r < 4; r++) acc[mt][nt][r] = 0.0f;

    #pragma unroll 1
    for (int cch = 0; cch < 8; cch++) {
        if (cch <= 5) { CP_WAIT2(); } else if (cch == 6) { CP_WAIT1(); } else { CP_WAIT0(); }
        __syncthreads();
        if (cch < 5) {
            const uint32_t dst = smb + (uint32_t)(OFF_K + ((cch + 3) & 3) * KSTR) * 4u;
            const int ecp = (cch + 3) * 16;
            #pragma unroll
            for (int i = 0; i < 4; i++) {
                const int o = t + 512 * i;
                const int s = o >> 2, jj = o & 3;
                cpa16(dst + (uint32_t)(s * PKC + jj * 4) * 4u,
                      Kw + (size_t)s * EW + ecp + jj * 4);
            }
            CP_COMMIT();
        }
        const uint32_t bufK = smb + (uint32_t)(OFF_K + (cch & 3) * KSTR) * 4u;
        const int ecp = cch * 16;
        #pragma unroll
        for (int kkp = 0; kkp < 16; kkp += 8) {
            uint32_t a[2][4], b[8][2];
            #pragma unroll
            for (int mt = 0; mt < 2; mt++)
                ldsm4(a[mt], aQbase + (uint32_t)(mt * 16 * PQF + ecp + kkp) * 4u);
            #pragma unroll
            for (int nt2 = 0; nt2 < 8; nt2 += 2) {
                uint32_t r[4];
                ldsm4(r, bufK + (uint32_t)((wn * 64 + nt2 * 8) * PKC + kkp) * 4u + bKoff);
                b[nt2][0] = r[0]; b[nt2][1] = r[1];
                b[nt2 + 1][0] = r[2]; b[nt2 + 1][1] = r[3];
            }
            #pragma unroll
            for (int mt = 0; mt < 2; mt++)
                #pragma unroll
                for (int nt = 0; nt < 8; nt++)
                    mma16(acc[mt][nt], a[mt], b[nt]);
        }
    }

    // ---------------- Softmax (fp32 on fragments) --------------------------
    float rmax[4], rinv[4];
    #pragma unroll
    for (int mt = 0; mt < 2; mt++)
        #pragma unroll
        for (int h = 0; h < 2; h++) {
            float m = -1e30f;
            #pragma unroll
            for (int nt = 0; nt < 8; nt++) {
                m = fmaxf(m, acc[mt][nt][2 * h]);
                m = fmaxf(m, acc[mt][nt][2 * h + 1]);
            }
            m = fmaxf(m, __shfl_xor_sync(0xFFFFFFFFu, m, 1));
            m = fmaxf(m, __shfl_xor_sync(0xFFFFFFFFu, m, 2));
            rmax[mt * 2 + h] = m;
        }
    __syncthreads();   // all phase-1 K/Q smem reads done — overlays now safe

    // ---- issue V chunks 0,1,2 (overlap the whole softmax) -----------------
    #pragma unroll
    for (int pc = 0; pc < 3; pc++) {
        const uint32_t dst = smb + (uint32_t)(OFF_V + pc * VSTR) * 4u;
        const int spb = pc * 32;
        #pragma unroll
        for (int i = 0; i < 4; i++) {
            const int o = t + 512 * i;
            const int f = o >> 3, jj = o & 7;
            cpa16(dst + (uint32_t)(f * PVT + jj * 4) * 4u,
                  Vw + (size_t)f * SP_ + spb + jj * 4);
        }
        CP_COMMIT();
    }

    if (q == 0) {
        #pragma unroll
        for (int mt = 0; mt < 2; mt++)
            #pragma unroll
            for (int h = 0; h < 2; h++)
                sRedM[(wm * 32 + mt * 16 + h * 8 + g) * 8 + wn] = rmax[mt * 2 + h];
    }
    __syncthreads();
    #pragma unroll
    for (int s = 0; s < 4; s++) {
        const int row = wm * 32 + (s >> 1) * 16 + (s & 1) * 8 + g;
        float m = sRedM[row * 8];
        #pragma unroll
        for (int w = 1; w < 8; w++) m = fmaxf(m, sRedM[row * 8 + w]);
        rmax[s] = m;
    }

    #pragma unroll
    for (int mt = 0; mt < 2; mt++)
        #pragma unroll
        for (int h = 0; h < 2; h++) {
            float s = 0.0f;
            #pragma unroll
            for (int nt = 0; nt < 8; nt++) {
                float p0 = __expf(acc[mt][nt][2 * h]     - rmax[mt * 2 + h]);
                float p1 = __expf(acc[mt][nt][2 * h + 1] - rmax[mt * 2 + h]);
                acc[mt][nt][2 * h]     = p0;
                acc[mt][nt][2 * h + 1] = p1;
                s += p0 + p1;
            }
            s += __shfl_xor_sync(0xFFFFFFFFu, s, 1);
            s += __shfl_xor_sync(0xFFFFFFFFu, s, 2);
            if (q == 0) sRedS[(wm * 32 + mt * 16 + h * 8 + g) * 8 + wn] = s;
        }
    __syncthreads();
    #pragma unroll
    for (int s = 0; s < 4; s++) {
        const int row = wm * 32 + (s >> 1) * 16 + (s & 1) * 8 + g;
        float sum = 0.0f;
        #pragma unroll
        for (int w = 0; w < 8; w++) sum += sRedS[row * 8 + w];
        rinv[s] = 1.0f / sum;
    }

    // Store unnormalized P (bf16 pairs) to sS
    #pragma unroll
    for (int mt = 0; mt < 2; mt++)
        #pragma unroll
        for (int h = 0; h < 2; h++) {
            const int row = wm * 32 + mt * 16 + h * 8 + g;
            #pragma unroll
            for (int nt = 0; nt < 8; nt++)
                sS[row * SPP + wn * 32 + nt * 4 + q] =
                    pk2(acc[mt][nt][2 * h], acc[mt][nt][2 * h + 1]);
        }

    // ---------------- Phase 2: out = P V -----------------------------------
    float acc2[2][4][4];
    #pragma unroll
    for (int mt = 0; mt < 2; mt++)
        #pragma unroll
        for (int nt = 0; nt < 4; nt++)
            #pragma unroll
            for (int r = 0; r < 4; r++) acc2[mt][nt][r] = 0.0f;

    #pragma unroll 1
    for (int cch = 0; cch < 8; cch++) {
        if (cch <= 5) { CP_WAIT2(); } else if (cch == 6) { CP_WAIT1(); } else { CP_WAIT0(); }
        __syncthreads();           // V chunk ready + (first iter) P visible
        if (cch < 5) {
            const uint32_t dst = smb + (uint32_t)(OFF_V + ((cch + 3) & 3) * VSTR) * 4u;
            const int spb = (cch + 3) * 32;
            #pragma unroll
            for (int i = 0; i < 4; i++) {
                const int o = t + 512 * i;
                const int f = o >> 3, jj = o & 7;
                cpa16(dst + (uint32_t)(f * PVT + jj * 4) * 4u,
                      Vw + (size_t)f * SP_ + spb + jj * 4);
            }
            CP_COMMIT();
        }
        const uint32_t bufV = smb + (uint32_t)(OFF_V + (cch & 3) * VSTR) * 4u;
        const int ktp = cch * 32;
        #pragma unroll
        for (int kkp = 0; kkp < 32; kkp += 8) {
            uint32_t a[2][4], b[4][2];
            #pragma unroll
            for (int mt = 0; mt < 2; mt++)
                ldsm4(a[mt], aSbase + (uint32_t)(mt * 16 * SPP + ktp + kkp) * 4u);
            #pragma unroll
            for (int nt2 = 0; nt2 < 4; nt2 += 2) {
                uint32_t r[4];
                ldsm4(r, bufV + (uint32_t)((wn * 32 + nt2 * 8) * PVT + kkp) * 4u + bVoff);
                b[nt2][0] = r[0]; b[nt2][1] = r[1];
                b[nt2 + 1][0] = r[2]; b[nt2 + 1][1] = r[3];
            }
            #pragma unroll
            for (int mt = 0; mt < 2; mt++)
                #pragma unroll
                for (int nt = 0; nt < 4; nt++)
                    mma16(acc2[mt][nt], a[mt], b[nt]);
        }
    }

    // Epilogue: normalize + store fp32
    #pragma unroll
    for (int mt = 0; mt < 2; mt++)
        #pragma unroll
        for (int h = 0; h < 2; h++) {
            const int row = q0 + wm * 32 + mt * 16 + h * 8 + g;
            const float inv = rinv[mt * 2 + h];
            #pragma unroll
            for (int nt = 0; nt < 4; nt++) {
                const int col = wn * 32 + nt * 8 + 2 * q;
                float2 v;
                v.x = acc2[mt][nt][2 * h]     * inv;
                v.y = acc2[mt][nt][2 * h + 1] * inv;
                *(float2*)&O[(size_t)row * E_ + col] = v;
            }
        }
}

// ---------------------------------------------------------------------------
extern "C" void kernel_launch(void* const* d_in, const int* in_sizes, int n_in,
                              void* d_out, int out_size)
{
    const float* query = (const float*)d_in[0];
    const float* key   = (const float*)d_in[1];
    const float* value = (const float*)d_in[2];
    const float* wq    = (const float*)d_in[3];
    const float* wk    = (const float*)d_in[4];
    const float* wv    = (const float*)d_in[5];
    const float* bq    = (const float*)d_in[6];
    const float* bk    = (const float*)d_in[7];
    const float* bv    = (const float*)d_in[8];
    float* out = (float*)d_out;

    const float qscale = 1.0f / sqrtf((float)E_);

    dim3 pgrid(S_ / 128, E_ / 128, 3 * BC_);
    proj_kernel<<<pgrid, 512>>>(query, key, value, wq, wk, wv, bq, bk, bv, qscale);

    const size_t smem = (size_t)ATT_WORDS * sizeof(uint32_t);
    cudaFuncSetAttribute(attn_kernel, cudaFuncAttributeMaxDynamicSharedMemorySize,
                         (int)smem);
    attn_kernel<<<dim3(S_ / 64, BC_), 512, smem>>>(out);
}

// round 12
// speedup vs baseline: 1.0455x; 1.0455x over previous
#include <cuda_runtime.h>
#include <math.h>
#include <stdint.h>

#define B_ 8
#define C_ 16
#define S_ 512
#define E_ 256
#define BC_ 128
#define EW  128   // bf16x2 words per row (E/2)
#define SP_ 256   // s-pairs (S/2)

// bf16 scratch: q/k as [s][e-pair]; v TRANSPOSED: [f][s-pair]
__device__ uint32_t g_q[(size_t)BC_ * S_ * EW];
__device__ uint32_t g_k[(size_t)BC_ * S_ * EW];
__device__ uint32_t g_v[(size_t)BC_ * E_ * SP_];

// ---------------------------------------------------------------------------
// helpers
// ---------------------------------------------------------------------------
__device__ __forceinline__ uint32_t pk2(float lo, float hi) {
    uint32_t r;
    asm("cvt.rn.bf16x2.f32 %0, %1, %2;" : "=r"(r) : "f"(hi), "f"(lo));
    return r;
}
__device__ __forceinline__ uint2 pk4(float4 v) {
    uint2 u; u.x = pk2(v.x, v.y); u.y = pk2(v.z, v.w); return u;
}
__device__ __forceinline__ void mma16(float* c, const uint32_t* a, const uint32_t* b) {
    asm volatile(
        "mma.sync.aligned.m16n8k16.row.col.f32.bf16.bf16.f32 "
        "{%0,%1,%2,%3}, {%4,%5,%6,%7}, {%8,%9}, {%0,%1,%2,%3};"
        : "+f"(c[0]), "+f"(c[1]), "+f"(c[2]), "+f"(c[3])
        : "r"(a[0]), "r"(a[1]), "r"(a[2]), "r"(a[3]), "r"(b[0]), "r"(b[1]));
}
__device__ __forceinline__ void ldsm4(uint32_t* r, uint32_t addr) {
    asm volatile("ldmatrix.sync.aligned.m8n8.x4.shared.b16 {%0,%1,%2,%3}, [%4];"
                 : "=r"(r[0]), "=r"(r[1]), "=r"(r[2]), "=r"(r[3]) : "r"(addr));
}
__device__ __forceinline__ void cpa16(uint32_t smem_addr, const void* gptr) {
    asm volatile("cp.async.cg.shared.global [%0], [%1], 16;"
                 :: "r"(smem_addr), "l"(gptr));
}
#define CP_COMMIT() asm volatile("cp.async.commit_group;")
#define CP_WAIT0()  asm volatile("cp.async.wait_group 0;")
#define CP_WAIT1()  asm volatile("cp.async.wait_group 1;")
#define CP_WAIT2()  asm volatile("cp.async.wait_group 2;")

// ---------------------------------------------------------------------------
// Projection (merged q/k/v) — R9 version + launch_bounds(256,2) for 2 CTAs/SM.
// CTA 128x128, 8 warps (2m x 4n), k-chunk 64.
// ---------------------------------------------------------------------------
#define PA  36
#define PBP 136
#define PT  68

__global__ __launch_bounds__(256, 2) void proj_kernel(
    const float* __restrict__ query, const float* __restrict__ key,
    const float* __restrict__ value,
    const float* __restrict__ wq, const float* __restrict__ wk,
    const float* __restrict__ wv,
    const float* __restrict__ bq, const float* __restrict__ bk,
    const float* __restrict__ bv, float qscale)
{
    __shared__ uint32_t pool[8960];      // sA(4608)+sB(4352); sT(8704) overlay
    uint32_t* sA = pool;
    uint32_t* sB = pool + 4608;
    uint32_t* sT = pool;

    const int zi    = blockIdx.z;
    const int which = zi >> 7;
    const int bc    = zi & (BC_ - 1);
    const int c     = bc % C_;

    const float *X, *W, *bp;
    uint32_t* Yw;
    float scale;
    if (which == 0)      { X = query; W = wq; bp = bq; Yw = g_q + (size_t)bc * S_ * EW; scale = qscale; }
    else if (which == 1) { X = key;   W = wk; bp = bk; Yw = g_k + (size_t)bc * S_ * EW; scale = 1.0f; }
    else                 { X = value; W = wv; bp = bv; Yw = g_v + (size_t)bc * E_ * SP_; scale = 1.0f; }
    X  += (size_t)bc * S_ * E_;
    W  += (size_t)c  * E_ * E_;
    bp += (size_t)c  * E_;

    const int m0 = blockIdx.x * 128;
    const int n0 = blockIdx.y * 128;
    const int t  = threadIdx.x;
    const int warp  = t >> 5;
    const int warpm = warp >> 2;
    const int warpn = warp & 3;
    const int lane  = t & 31;
    const int g = lane >> 2;
    const int q = lane & 3;

    const int arow  = (lane & 7) + (((lane >> 3) & 1) << 3);
    const int akadd = (lane >> 4) << 2;
    const uint32_t smbA = (uint32_t)__cvta_generic_to_shared(sA);
    const uint32_t aBase = smbA + (uint32_t)(arow * PA + akadd) * 4u;

    float acc[4][4][4];
    #pragma unroll
    for (int i = 0; i < 4; i++)
        #pragma unroll
        for (int j = 0; j < 4; j++)
            #pragma unroll
            for (int r = 0; r < 4; r++) acc[i][j][r] = 0.0f;

    for (int k0 = 0; k0 < E_; k0 += 64) {
        #pragma unroll
        for (int i = 0; i < 8; i++) {
            const int idx = t + 256 * i;
            const int row = idx >> 4, c4 = idx & 15;
            *(uint2*)&sA[row * PA + c4 * 2] =
                pk4(*(const float4*)&X[(size_t)(m0 + row) * E_ + k0 + 4 * c4]);
        }
        #pragma unroll
        for (int i = 0; i < 4; i++) {
            const int idx = t + 256 * i;
            const int kp = idx >> 5, n4 = (idx & 31) * 4;
            const float4 w0 = *(const float4*)&W[(size_t)(k0 + 2 * kp)     * E_ + n0 + n4];
            const float4 w1 = *(const float4*)&W[(size_t)(k0 + 2 * kp + 1) * E_ + n0 + n4];
            uint4 u;
            u.x = pk2(w0.x, w1.x); u.y = pk2(w0.y, w1.y);
            u.z = pk2(w0.z, w1.z); u.w = pk2(w0.w, w1.w);
            *(uint4*)&sB[kp * PBP + n4] = u;
        }
        __syncthreads();

        #pragma unroll
        for (int kkp = 0; kkp < 32; kkp += 8) {
            uint32_t a[4][4], b[4][2];
            #pragma unroll
            for (int mt = 0; mt < 4; mt++)
                ldsm4(a[mt], aBase + (uint32_t)((warpm * 64 + mt * 16) * PA + kkp) * 4u);
            #pragma unroll
            for (int nt = 0; nt < 4; nt++) {
                const int n = warpn * 32 + nt * 8 + g;
                b[nt][0] = sB[(kkp + q) * PBP + n];
                b[nt][1] = sB[(kkp + q + 4) * PBP + n];
            }
            #pragma unroll
            for (int mt = 0; mt < 4; mt++)
                #pragma unroll
                for (int nt = 0; nt < 4; nt++)
                    mma16(acc[mt][nt], a[mt], b[nt]);
        }
        __syncthreads();
    }

    if (which != 2) {
        #pragma unroll
        for (int nt = 0; nt < 4; nt++) {
            const int col = n0 + warpn * 32 + nt * 8 + 2 * q;
            const float b0v = bp[col], b1v = bp[col + 1];
            #pragma unroll
            for (int mt = 0; mt < 4; mt++) {
                const int row = m0 + warpm * 64 + mt * 16 + g;
                const float v00 = fmaxf(acc[mt][nt][0] + b0v, 0.0f) * scale;
                const float v01 = fmaxf(acc[mt][nt][1] + b1v, 0.0f) * scale;
                const float v10 = fmaxf(acc[mt][nt][2] + b0v, 0.0f) * scale;
                const float v11 = fmaxf(acc[mt][nt][3] + b1v, 0.0f) * scale;
                const int cw = (n0 >> 1) + warpn * 16 + nt * 4 + q;
                Yw[(size_t)row * EW + cw]       = pk2(v00, v01);
                Yw[(size_t)(row + 8) * EW + cw] = pk2(v10, v11);
            }
        }
    } else {
        #pragma unroll
        for (int nt = 0; nt < 4; nt++) {
            const int col = n0 + warpn * 32 + nt * 8 + 2 * q;
            const float b0v = bp[col], b1v = bp[col + 1];
            #pragma unroll
            for (int mt = 0; mt < 4; mt++) {
                const float v00 = fmaxf(acc[mt][nt][0] + b0v, 0.0f);
                const float v01 = fmaxf(acc[mt][nt][1] + b1v, 0.0f);
                const float v10 = fmaxf(acc[mt][nt][2] + b0v, 0.0f);
                const float v11 = fmaxf(acc[mt][nt][3] + b1v, 0.0f);
                const float p00 = __shfl_xor_sync(0xFFFFFFFFu, v00, 4);
                const float p01 = __shfl_xor_sync(0xFFFFFFFFu, v01, 4);
                const float p10 = __shfl_xor_sync(0xFFFFFFFFu, v10, 4);
                const float p11 = __shfl_xor_sync(0xFFFFFFFFu, v11, 4);
                if ((g & 1) == 0) {
                    const int lcol = warpn * 32 + nt * 8 + 2 * q;
                    const int lsp  = (warpm * 64 + mt * 16 + g) >> 1;
                    sT[lcol * PT + lsp]           = pk2(v00, p00);
                    sT[(lcol + 1) * PT + lsp]     = pk2(v01, p01);
                    sT[lcol * PT + lsp + 4]       = pk2(v10, p10);
                    sT[(lcol + 1) * PT + lsp + 4] = pk2(v11, p11);
                }
            }
        }
        __syncthreads();
        const int spb = m0 >> 1;
        #pragma unroll
        for (int i = 0; i < 8; i++) {
            const int o = t + 256 * i;
            const int col = o >> 4, j = o & 15;
            *(uint4*)&Yw[(size_t)(n0 + col) * SP_ + spb + j * 4] =
                *(uint4*)&sT[col * PT + j * 4];
        }
    }
}

// ---------------------------------------------------------------------------
// Attention (R9 base): 64 q-rows/CTA, 512 threads (2m x 8n), scores in regs,
// 3-stage cp.async pipelines, ldmatrix operands. NEW: fused 1-barrier softmax.
// ---------------------------------------------------------------------------
#define PQF 132
#define PKC 20
#define SPP 260
#define PVT 36

#define OFF_SQ 0             // 64*132 = 8448
#define OFF_K  8448          // 3 x 10240 -> ends 39168
#define KSTR   10240
#define OFF_SS 0             // 64*260 = 16640 (overlay)
#define OFF_V  16640         // 3 x 9216 -> ends 44288
#define VSTR   9216
#define OFF_RD 44288         // 1024 floats: float2 [64 rows][8 wn]
#define ATT_WORDS 45312      // 181248 B

__global__ __launch_bounds__(512, 1) void attn_kernel(float* __restrict__ out)
{
    extern __shared__ uint32_t smu[];
    uint32_t* sQ = smu + OFF_SQ;
    uint32_t* sS = smu + OFF_SS;
    float* sRed = (float*)(smu + OFF_RD);          // float2 per [row][wn]

    const uint32_t smb = (uint32_t)__cvta_generic_to_shared(smu);

    const int bc = blockIdx.y;
    const int q0 = blockIdx.x * 64;
    const uint32_t* Qw = g_q + (size_t)bc * S_ * EW;
    const uint32_t* Kw = g_k + (size_t)bc * S_ * EW;
    const uint32_t* Vw = g_v + (size_t)bc * E_ * SP_;
    float*          O  = out + (size_t)bc * S_ * E_;

    const int t    = threadIdx.x;
    const int warp = t >> 5;
    const int wm   = warp >> 3;
    const int wn   = warp & 7;
    const int lane = t & 31;
    const int g = lane >> 2;
    const int q = lane & 3;

    const int arow  = (lane & 7) + (((lane >> 3) & 1) << 3);
    const int akadd = (lane >> 4) << 2;
    const int brow  = (lane & 7) + ((lane >> 4) << 3);
    const int bkadd = ((lane >> 3) & 1) << 2;

    const uint32_t aQbase = smb + (uint32_t)(OFF_SQ + (wm * 32 + arow) * PQF + akadd) * 4u;
    const uint32_t aSbase = smb + (uint32_t)(OFF_SS + (wm * 32 + arow) * SPP + akadd) * 4u;
    const uint32_t bKoff  = (uint32_t)(brow * PKC + bkadd) * 4u;
    const uint32_t bVoff  = (uint32_t)(brow * PVT + bkadd) * 4u;

    // ---- issue K chunks 0,1 (3-stage prologue) ---------------------------
    #pragma unroll
    for (int pc = 0; pc < 2; pc++) {
        const uint32_t dst = smb + (uint32_t)(OFF_K + pc * KSTR) * 4u;
        const int ecp = pc * 16;
        #pragma unroll
        for (int i = 0; i < 4; i++) {
            const int o = t + 512 * i;
            const int s = o >> 2, jj = o & 3;
            cpa16(dst + (uint32_t)(s * PKC + jj * 4) * 4u,
                  Kw + (size_t)s * EW + ecp + jj * 4);
        }
        CP_COMMIT();
    }

    // ---- stage whole Q tile (64 x 128 words) -----------------------------
    #pragma unroll
    for (int i = 0; i < 4; i++) {
        const int o = t + 512 * i;
        const int row = o >> 5, j = o & 31;
        *(uint4*)&sQ[row * PQF + j * 4] =
            *(const uint4*)&Qw[(size_t)(q0 + row) * EW + j * 4];
    }

    // ---------------- Phase 1: scores = Q K^T ------------------------------
    float acc[2][8][4];
    #pragma unroll
    for (int mt = 0; mt < 2; mt++)
        #pragma unroll
        for (int nt = 0; nt < 8; nt++)
            #pragma unroll
            for (int r = 0; r < 4; r++) acc[mt][nt][r] = 0.0f;

    #pragma unroll 1
    for (int cch = 0; cch < 8; cch++) {
        if (cch >= 6) { CP_WAIT0(); } else { CP_WAIT1(); }
        __syncthreads();
        if (cch < 6) {
            const uint32_t dst = smb + (uint32_t)(OFF_K + ((cch + 2) % 3) * KSTR) * 4u;
            const int ecp = (cch + 2) * 16;
            #pragma unroll
            for (int i = 0; i < 4; i++) {
                const int o = t + 512 * i;
                const int s = o >> 2, jj = o & 3;
                cpa16(dst + (uint32_t)(s * PKC + jj * 4) * 4u,
                      Kw + (size_t)s * EW + ecp + jj * 4);
            }
            CP_COMMIT();
        }
        const uint32_t bufK = smb + (uint32_t)(OFF_K + (cch % 3) * KSTR) * 4u;
        const int ecp = cch * 16;
        #pragma unroll
        for (int kkp = 0; kkp < 16; kkp += 8) {
            uint32_t a[2][4], b[8][2];
            #pragma unroll
            for (int mt = 0; mt < 2; mt++)
                ldsm4(a[mt], aQbase + (uint32_t)(mt * 16 * PQF + ecp + kkp) * 4u);
            #pragma unroll
            for (int nt2 = 0; nt2 < 8; nt2 += 2) {
                uint32_t r[4];
                ldsm4(r, bufK + (uint32_t)((wn * 64 + nt2 * 8) * PKC + kkp) * 4u + bKoff);
                b[nt2][0] = r[0]; b[nt2][1] = r[1];
                b[nt2 + 1][0] = r[2]; b[nt2 + 1][1] = r[3];
            }
            #pragma unroll
            for (int mt = 0; mt < 2; mt++)
                #pragma unroll
                for (int nt = 0; nt < 8; nt++)
                    mma16(acc[mt][nt], a[mt], b[nt]);
        }
    }

    // ---------------- Fused softmax: one cross-warp exchange ---------------
    // slot s = mt*2+h owns row wm*32 + mt*16 + h*8 + g (16 cols per warp).
    float mloc[4], sloc[4];
    #pragma unroll
    for (int mt = 0; mt < 2; mt++)
        #pragma unroll
        for (int h = 0; h < 2; h++) {
            float m = -1e30f;
            #pragma unroll
            for (int nt = 0; nt < 8; nt++) {
                m = fmaxf(m, acc[mt][nt][2 * h]);
                m = fmaxf(m, acc[mt][nt][2 * h + 1]);
            }
            m = fmaxf(m, __shfl_xor_sync(0xFFFFFFFFu, m, 1));
            m = fmaxf(m, __shfl_xor_sync(0xFFFFFFFFu, m, 2));
            mloc[mt * 2 + h] = m;
        }
    __syncthreads();   // all phase-1 K/Q smem reads done — overlays now safe

    // ---- issue V chunks 0,1,2 (overlap the exp pass below) ----------------
    #pragma unroll
    for (int pc = 0; pc < 3; pc++) {
        const uint32_t dst = smb + (uint32_t)(OFF_V + pc * VSTR) * 4u;
        const int spb = pc * 32;
        #pragma unroll
        for (int i = 0; i < 4; i++) {
            const int o = t + 512 * i;
            const int f = o >> 3, jj = o & 7;
            cpa16(dst + (uint32_t)(f * PVT + jj * 4) * 4u,
                  Vw + (size_t)f * SP_ + spb + jj * 4);
        }
        CP_COMMIT();
    }

    // local exp + local sum, publish (m_w, s_w) as one float2
    #pragma unroll
    for (int mt = 0; mt < 2; mt++)
        #pragma unroll
        for (int h = 0; h < 2; h++) {
            const float m = mloc[mt * 2 + h];
            float s = 0.0f;
            #pragma unroll
            for (int nt = 0; nt < 8; nt++) {
                float p0 = __expf(acc[mt][nt][2 * h]     - m);
                float p1 = __expf(acc[mt][nt][2 * h + 1] - m);
                acc[mt][nt][2 * h]     = p0;
                acc[mt][nt][2 * h + 1] = p1;
                s += p0 + p1;
            }
            s += __shfl_xor_sync(0xFFFFFFFFu, s, 1);
            s += __shfl_xor_sync(0xFFFFFFFFu, s, 2);
            sloc[mt * 2 + h] = s;
            if (q == 0) {
                const int row = wm * 32 + mt * 16 + h * 8 + g;
                *(float2*)&sRed[(row * 8 + wn) * 2] = make_float2(m, s);
            }
        }
    __syncthreads();

    // combine: M = max m_w ; S = sum s_w * e^{m_w - M} ; fac = e^{m_loc - M}
    float fac[4], rinv[4];
    #pragma unroll
    for (int s4 = 0; s4 < 4; s4++) {
        const int row = wm * 32 + (s4 >> 1) * 16 + (s4 & 1) * 8 + g;
        float2 mw[8];
        #pragma unroll
        for (int w = 0; w < 8; w++) mw[w] = *(const float2*)&sRed[(row * 8 + w) * 2];
        float M = mw[0].x;
        #pragma unroll
        for (int w = 1; w < 8; w++) M = fmaxf(M, mw[w].x);
        float S = 0.0f;
        #pragma unroll
        for (int w = 0; w < 8; w++) S += mw[w].y * __expf(mw[w].x - M);
        fac[s4]  = __expf(mloc[s4] - M);
        rinv[s4] = 1.0f / S;
    }
    (void)sloc;

    // Store unnormalized P (bf16 pairs, rescaled by fac) to sS
    #pragma unroll
    for (int mt = 0; mt < 2; mt++)
        #pragma unroll
        for (int h = 0; h < 2; h++) {
            const int row = wm * 32 + mt * 16 + h * 8 + g;
            const float f = fac[mt * 2 + h];
            #pragma unroll
            for (int nt = 0; nt < 8; nt++)
                sS[row * SPP + wn * 32 + nt * 4 + q] =
                    pk2(acc[mt][nt][2 * h] * f, acc[mt][nt][2 * h + 1] * f);
        }

    // ---------------- Phase 2: out = P V -----------------------------------
    float acc2[2][4][4];
    #pragma unroll
    for (int mt = 0; mt < 2; mt++)
        #pragma unroll
        for (int nt = 0; nt < 4; nt++)
            #pragma unroll
            for (int r = 0; r < 4; r++) acc2[mt][nt][r] = 0.0f;

    #pragma unroll 1
    for (int cch = 0; cch < 8; cch++) {
        if (cch >= 6) { CP_WAIT0(); } else { CP_WAIT1(); }
        __syncthreads();           // V chunk ready + (first iter) P visible
        if (cch < 6) {
            const uint32_t dst = smb + (uint32_t)(OFF_V + ((cch + 2) % 3) * VSTR) * 4u;
            const int spb = (cch + 2) * 32;
            #pragma unroll
            for (int i = 0; i < 4; i++) {
                const int o = t + 512 * i;
                const int f = o >> 3, jj = o & 7;
                cpa16(dst + (uint32_t)(f * PVT + jj * 4) * 4u,
                      Vw + (size_t)f * SP_ + spb + jj * 4);
            }
            CP_COMMIT();
        }
        const uint32_t bufV = smb + (uint32_t)(OFF_V + (cch % 3) * VSTR) * 4u;
        const int ktp = cch * 32;
        #pragma unroll
        for (int kkp = 0; kkp < 32; kkp += 8) {
            uint32_t a[2][4], b[4][2];
            #pragma unroll
            for (int mt = 0; mt < 2; mt++)
                ldsm4(a[mt], aSbase + (uint32_t)(mt * 16 * SPP + ktp + kkp) * 4u);
            #pragma unroll
            for (int nt2 = 0; nt2 < 4; nt2 += 2) {
                uint32_t r[4];
                ldsm4(r, bufV + (uint32_t)((wn * 32 + nt2 * 8) * PVT + kkp) * 4u + bVoff);
                b[nt2][0] = r[0]; b[nt2][1] = r[1];
                b[nt2 + 1][0] = r[2]; b[nt2 + 1][1] = r[3];
            }
            #pragma unroll
            for (int mt = 0; mt < 2; mt++)
                #pragma unroll
                for (int nt = 0; nt < 4; nt++)
                    mma16(acc2[mt][nt], a[mt], b[nt]);
        }
    }

    // Epilogue: normalize + store fp32
    #pragma unroll
    for (int mt = 0; mt < 2; mt++)
        #pragma unroll
        for (int h = 0; h < 2; h++) {
            const int row = q0 + wm * 32 + mt * 16 + h * 8 + g;
            const float inv = rinv[mt * 2 + h];
            #pragma unroll
            for (int nt = 0; nt < 4; nt++) {
                const int col = wn * 32 + nt * 8 + 2 * q;
                float2 v;
                v.x = acc2[mt][nt][2 * h]     * inv;
                v.y = acc2[mt][nt][2 * h + 1] * inv;
                *(float2*)&O[(size_t)row * E_ + col] = v;
            }
        }
}

// ---------------------------------------------------------------------------
extern "C" void kernel_launch(void* const* d_in, const int* in_sizes, int n_in,
                              void* d_out, int out_size)
{
    const float* query = (const float*)d_in[0];
    const float* key   = (const float*)d_in[1];
    const float* value = (const float*)d_in[2];
    const float* wq    = (const float*)d_in[3];
    const float* wk    = (const float*)d_in[4];
    const float* wv    = (const float*)d_in[5];
    const float* bq    = (const float*)d_in[6];
    const float* bk    = (const float*)d_in[7];
    const float* bv    = (const float*)d_in[8];
    float* out = (float*)d_out;

    const float qscale = 1.0f / sqrtf((float)E_);

    dim3 pgrid(S_ / 128, E_ / 128, 3 * BC_);
    proj_kernel<<<pgrid, 256>>>(query, key, value, wq, wk, wv, bq, bk, bv, qscale);

    const size_t smem = (size_t)ATT_WORDS * sizeof(uint32_t);
    cudaFuncSetAttribute(attn_kernel, cudaFuncAttributeMaxDynamicSharedMemorySize,
                         (int)smem);
    attn_kernel<<<dim3(S_ / 64, BC_), 512, smem>>>(out);
}